// round 1
// baseline (speedup 1.0000x reference)
#include <cuda_runtime.h>

#define NG    64            // b*g groups
#define NN    2048          // nodes per group
#define F     128           // IN_F == 2*OUT_F == 128
#define H     4             // heads
#define SPLIT 8             // n-chunks per group
#define CHUNK (NN/SPLIT)    // 256 rows per CTA
#define T1    256           // threads in k1
#define WARPS (T1/32)       // 8
#define RPW   (CHUNK/WARPS) // 32 rows per warp
#define PSTRIDE (F+2)       // v[128], m, s

__device__ float g_wa[H*F];
__device__ float g_part[NG*SPLIT*H*PSTRIDE];

// ---------------------------------------------------------------------------
// k0: wa_h[i] = sum_j W_h[i][j] * a_h[j]   (one tiny block)
// ---------------------------------------------------------------------------
__global__ void k0_wa(const float* __restrict__ W1, const float* __restrict__ a1,
                      const float* __restrict__ W2, const float* __restrict__ a2,
                      const float* __restrict__ W3, const float* __restrict__ a3,
                      const float* __restrict__ W4, const float* __restrict__ a4) {
    __shared__ float sa[H][F];
    const float* Ws[H] = {W1, W2, W3, W4};
    const float* as[H] = {a1, a2, a3, a4};
    int tid = threadIdx.x;                 // 512 threads
    {
        int h = tid >> 7, j = tid & (F-1);
        sa[h][j] = as[h][j];
    }
    __syncthreads();
    int h = tid >> 7, i = tid & (F-1);
    const float* Wp = Ws[h] + i * F;
    float s = 0.f;
    #pragma unroll 8
    for (int j = 0; j < F; j++) s += Wp[j] * sa[h][j];
    g_wa[h*F + i] = s;
}

// ---------------------------------------------------------------------------
// k1: streaming pass over features. Warp-per-row, online softmax per head.
// grid = (NG, SPLIT), block = 256
// ---------------------------------------------------------------------------
__global__ void __launch_bounds__(T1) k1_pool(const float* __restrict__ feat) {
    const int grp = blockIdx.x, chunk = blockIdx.y;
    const int tid = threadIdx.x, lane = tid & 31, warp = tid >> 5;

    // wa in registers: lane owns cols 4*lane..4*lane+3 for each head
    float4 wa[H];
    #pragma unroll
    for (int h = 0; h < H; h++)
        wa[h] = *reinterpret_cast<const float4*>(&g_wa[h*F + lane*4]);

    const float* base = feat +
        ((size_t)grp * NN + (size_t)chunk * CHUNK + (size_t)warp * RPW) * F;

    float  m[H], s[H];
    float4 v[H];
    #pragma unroll
    for (int h = 0; h < H; h++) {
        m[h] = -1e30f; s[h] = 0.f; v[h] = make_float4(0.f, 0.f, 0.f, 0.f);
    }

    #pragma unroll 1
    for (int r = 0; r < RPW; r += 4) {
        float4 f[4];
        #pragma unroll
        for (int q = 0; q < 4; q++)
            f[q] = *reinterpret_cast<const float4*>(base + (size_t)(r+q)*F + lane*4);

        #pragma unroll
        for (int q = 0; q < 4; q++) {
            float d[H];
            #pragma unroll
            for (int h = 0; h < H; h++)
                d[h] = f[q].x*wa[h].x + f[q].y*wa[h].y + f[q].z*wa[h].z + f[q].w*wa[h].w;
            // warp all-reduce (4 independent values)
            #pragma unroll
            for (int off = 16; off; off >>= 1) {
                #pragma unroll
                for (int h = 0; h < H; h++)
                    d[h] += __shfl_xor_sync(0xffffffffu, d[h], off);
            }
            #pragma unroll
            for (int h = 0; h < H; h++) {
                if (d[h] > m[h]) {
                    float c = __expf(m[h] - d[h]);
                    s[h] *= c;
                    v[h].x *= c; v[h].y *= c; v[h].z *= c; v[h].w *= c;
                    m[h] = d[h];
                }
                float p = __expf(d[h] - m[h]);
                s[h] += p;
                v[h].x += p*f[q].x; v[h].y += p*f[q].y;
                v[h].z += p*f[q].z; v[h].w += p*f[q].w;
            }
        }
    }

    // cross-warp combine
    __shared__ float sm_m[WARPS][H], sm_s[WARPS][H];
    __shared__ float sm_v[WARPS][H][F];
    #pragma unroll
    for (int h = 0; h < H; h++) {
        if (lane == 0) { sm_m[warp][h] = m[h]; sm_s[warp][h] = s[h]; }
        sm_v[warp][h][lane*4+0] = v[h].x;
        sm_v[warp][h][lane*4+1] = v[h].y;
        sm_v[warp][h][lane*4+2] = v[h].z;
        sm_v[warp][h][lane*4+3] = v[h].w;
    }
    __syncthreads();

    float* out = g_part + (size_t)((grp*SPLIT + chunk) * H) * PSTRIDE;
    for (int idx = tid; idx < H*F; idx += T1) {
        int h = idx >> 7, i = idx & (F-1);
        float mm = sm_m[0][h];
        #pragma unroll
        for (int w = 1; w < WARPS; w++) mm = fmaxf(mm, sm_m[w][h]);
        float vv = 0.f, ss = 0.f;
        #pragma unroll
        for (int w = 0; w < WARPS; w++) {
            float c = __expf(sm_m[w][h] - mm);
            vv += sm_v[w][h][i] * c;
            ss += sm_s[w][h] * c;
        }
        float* oh = out + h * PSTRIDE;
        oh[i] = vv;
        if (i == 0) { oh[F] = mm; oh[F+1] = ss; }
    }
}

// ---------------------------------------------------------------------------
// k2: combine split partials -> pooled feature; apply W_h; concat @ Wo; ELU.
// grid = NG, block = 128 (thread = output column i)
// ---------------------------------------------------------------------------
__global__ void __launch_bounds__(128) k2_epi(
        const float* __restrict__ W1, const float* __restrict__ W2,
        const float* __restrict__ W3, const float* __restrict__ W4,
        const float* __restrict__ Wo, float* __restrict__ out) {
    const int grp = blockIdx.x, tid = threadIdx.x;
    __shared__ float pooled[H][F];
    __shared__ float multi[H*F];

    const float* part = g_part + (size_t)grp * SPLIT * H * PSTRIDE;
    #pragma unroll
    for (int h = 0; h < H; h++) {
        float mm = -1e30f;
        #pragma unroll
        for (int c = 0; c < SPLIT; c++)
            mm = fmaxf(mm, part[(c*H + h)*PSTRIDE + F]);
        float vv = 0.f, ss = 0.f;
        #pragma unroll
        for (int c = 0; c < SPLIT; c++) {
            const float* pc = part + (c*H + h)*PSTRIDE;
            float e = __expf(pc[F] - mm);
            vv += pc[tid]   * e;
            ss += pc[F+1] * e;
        }
        pooled[h][tid] = vv / ss;
    }
    __syncthreads();

    const float* Ws[H] = {W1, W2, W3, W4};
    #pragma unroll
    for (int h = 0; h < H; h++) {
        const float* Wp = Ws[h];
        float acc = 0.f;
        #pragma unroll 8
        for (int i = 0; i < F; i++) acc += pooled[h][i] * Wp[i*F + tid];
        multi[h*F + tid] = acc;
    }
    __syncthreads();

    if (tid < 64) {
        float acc = 0.f;
        #pragma unroll 8
        for (int k = 0; k < H*F; k++) acc += multi[k] * Wo[k*64 + tid];
        out[grp*64 + tid] = (acc > 0.f) ? acc : expm1f(acc);
    }
}

// ---------------------------------------------------------------------------
extern "C" void kernel_launch(void* const* d_in, const int* in_sizes, int n_in,
                              void* d_out, int out_size) {
    const float* feat = (const float*)d_in[0];
    const float* W1   = (const float*)d_in[1];
    const float* a1   = (const float*)d_in[2];
    const float* W2   = (const float*)d_in[3];
    const float* a2   = (const float*)d_in[4];
    const float* W3   = (const float*)d_in[5];
    const float* a3   = (const float*)d_in[6];
    const float* W4   = (const float*)d_in[7];
    const float* a4   = (const float*)d_in[8];
    const float* Wo   = (const float*)d_in[9];
    float* out = (float*)d_out;

    k0_wa<<<1, 512>>>(W1, a1, W2, a2, W3, a3, W4, a4);
    k1_pool<<<dim3(NG, SPLIT), T1>>>(feat);
    k2_epi<<<NG, 128>>>(W1, W2, W3, W4, Wo, out);
}

// round 2
// speedup vs baseline: 1.5067x; 1.5067x over previous
#include <cuda_runtime.h>

#define NG     64            // b*g groups
#define NN     2048          // nodes per group
#define F      128           // IN_F == 2*OUT_F == 128
#define H      4             // heads
#define SPLIT  16            // chunks per group
#define CHUNK  128           // rows per CTA
#define TB     128           // threads in kB
#define PSTRIDE (F+2)        // v[128], m, s
#define XSTRIDE 132          // padded row stride in smem (conflict-free, 16B aligned)

__device__ float g_wa[H*F];
__device__ float g_part[NG*SPLIT*H*PSTRIDE];

// ---------------------------------------------------------------------------
// k0: wa_h = W_h @ a_h.  grid=4 (head per block), block=256 (8 warps x 16 outs)
// ---------------------------------------------------------------------------
__global__ void __launch_bounds__(256) k0_wa(
        const float* __restrict__ W1, const float* __restrict__ a1,
        const float* __restrict__ W2, const float* __restrict__ a2,
        const float* __restrict__ W3, const float* __restrict__ a3,
        const float* __restrict__ W4, const float* __restrict__ a4) {
    const float* Ws[H] = {W1, W2, W3, W4};
    const float* as[H] = {a1, a2, a3, a4};
    int head = blockIdx.x;
    int lane = threadIdx.x & 31, warp = threadIdx.x >> 5;
    const float* W = Ws[head];
    float4 a4v = *reinterpret_cast<const float4*>(as[head] + lane*4);
    #pragma unroll
    for (int o = 0; o < 16; o++) {
        int i = warp*16 + o;
        float4 w = *reinterpret_cast<const float4*>(W + i*F + lane*4);
        float d = w.x*a4v.x + w.y*a4v.y + w.z*a4v.z + w.w*a4v.w;
        #pragma unroll
        for (int off = 16; off; off >>= 1)
            d += __shfl_xor_sync(0xffffffffu, d, off);
        if (lane == 0) g_wa[head*F + i] = d;
    }
}

// ---------------------------------------------------------------------------
// kB: stream features; per-CTA chunk softmax partials. grid=(NG,SPLIT), block=128
// ---------------------------------------------------------------------------
__global__ void __launch_bounds__(TB) kB_pool(const float* __restrict__ feat) {
    __shared__ float sx[CHUNK*XSTRIDE];   // staged chunk, padded rows
    __shared__ float swa[H*F];
    __shared__ float dlog[H][CHUNK];
    __shared__ float pp[H][CHUNK];
    __shared__ float sm_m[H];

    const int grp = blockIdx.x, chunk = blockIdx.y;
    const int t = threadIdx.x, lane = t & 31, w = t >> 5;

    // copy wa to smem
    #pragma unroll
    for (int r = 0; r < H; r++) swa[t + r*TB] = g_wa[t + r*TB];

    // Phase0: coalesced load -> smem (warp writes one full row per k: conflict-free)
    const float4* src = reinterpret_cast<const float4*>(
        feat + ((size_t)grp*NN + (size_t)chunk*CHUNK) * F);
    #pragma unroll
    for (int k = 0; k < 32; k++) {
        int q = t + k*TB;
        float4 f = src[q];
        int row = q >> 5, c4 = q & 31;
        *reinterpret_cast<float4*>(sx + row*XSTRIDE + c4*4) = f;
    }
    __syncthreads();

    // Phase1: thread t = row t; 4 head-dots, no shuffles
    float d0 = 0.f, d1 = 0.f, d2 = 0.f, d3 = 0.f;
    const float* xr = sx + t*XSTRIDE;
    #pragma unroll 8
    for (int j4 = 0; j4 < 32; j4++) {
        float4 f  = *reinterpret_cast<const float4*>(xr + j4*4);
        float4 w0 = *reinterpret_cast<const float4*>(swa + 0*F + j4*4);
        float4 w1 = *reinterpret_cast<const float4*>(swa + 1*F + j4*4);
        float4 w2 = *reinterpret_cast<const float4*>(swa + 2*F + j4*4);
        float4 w3 = *reinterpret_cast<const float4*>(swa + 3*F + j4*4);
        d0 += f.x*w0.x + f.y*w0.y + f.z*w0.z + f.w*w0.w;
        d1 += f.x*w1.x + f.y*w1.y + f.z*w1.z + f.w*w1.w;
        d2 += f.x*w2.x + f.y*w2.y + f.z*w2.z + f.w*w2.w;
        d3 += f.x*w3.x + f.y*w3.y + f.z*w3.z + f.w*w3.w;
    }
    dlog[0][t] = d0; dlog[1][t] = d1; dlog[2][t] = d2; dlog[3][t] = d3;
    __syncthreads();

    // block max per head (warp w handles head w)
    if (w < H) {
        float m = fmaxf(fmaxf(dlog[w][lane], dlog[w][lane+32]),
                        fmaxf(dlog[w][lane+64], dlog[w][lane+96]));
        #pragma unroll
        for (int off = 16; off; off >>= 1)
            m = fmaxf(m, __shfl_xor_sync(0xffffffffu, m, off));
        if (lane == 0) sm_m[w] = m;
    }
    __syncthreads();

    float p0 = __expf(d0 - sm_m[0]);
    float p1 = __expf(d1 - sm_m[1]);
    float p2 = __expf(d2 - sm_m[2]);
    float p3 = __expf(d3 - sm_m[3]);
    pp[0][t] = p0; pp[1][t] = p1; pp[2][t] = p2; pp[3][t] = p3;
    __syncthreads();

    float* out = g_part + (size_t)((grp*SPLIT + chunk) * H) * PSTRIDE;
    if (w < H) {
        float s = pp[w][lane] + pp[w][lane+32] + pp[w][lane+64] + pp[w][lane+96];
        #pragma unroll
        for (int off = 16; off; off >>= 1)
            s += __shfl_xor_sync(0xffffffffu, s, off);
        if (lane == 0) { out[w*PSTRIDE + F] = sm_m[w]; out[w*PSTRIDE + F + 1] = s; }
    }

    // Phase2: thread t = column t; weighted sums over rows
    float v0 = 0.f, v1 = 0.f, v2 = 0.f, v3 = 0.f;
    #pragma unroll 4
    for (int t4 = 0; t4 < 32; t4++) {
        float4 q0 = *reinterpret_cast<const float4*>(&pp[0][t4*4]);
        float4 q1 = *reinterpret_cast<const float4*>(&pp[1][t4*4]);
        float4 q2 = *reinterpret_cast<const float4*>(&pp[2][t4*4]);
        float4 q3 = *reinterpret_cast<const float4*>(&pp[3][t4*4]);
        float x0 = sx[(t4*4+0)*XSTRIDE + t];
        float x1 = sx[(t4*4+1)*XSTRIDE + t];
        float x2 = sx[(t4*4+2)*XSTRIDE + t];
        float x3 = sx[(t4*4+3)*XSTRIDE + t];
        v0 += q0.x*x0 + q0.y*x1 + q0.z*x2 + q0.w*x3;
        v1 += q1.x*x0 + q1.y*x1 + q1.z*x2 + q1.w*x3;
        v2 += q2.x*x0 + q2.y*x1 + q2.z*x2 + q2.w*x3;
        v3 += q3.x*x0 + q3.y*x1 + q3.z*x2 + q3.w*x3;
    }
    out[0*PSTRIDE + t] = v0;
    out[1*PSTRIDE + t] = v1;
    out[2*PSTRIDE + t] = v2;
    out[3*PSTRIDE + t] = v3;
}

// ---------------------------------------------------------------------------
// k2: combine partials, apply W_h, concat @ Wo, ELU. grid=NG, block=256
// ---------------------------------------------------------------------------
__global__ void __launch_bounds__(256) k2_epi(
        const float* __restrict__ W1, const float* __restrict__ W2,
        const float* __restrict__ W3, const float* __restrict__ W4,
        const float* __restrict__ Wo, float* __restrict__ out) {
    __shared__ float pooled[H][F];
    __shared__ float multi[H*F];
    __shared__ float red[4][64];
    const int grp = blockIdx.x, t = threadIdx.x;
    const float* part = g_part + (size_t)grp * SPLIT * H * PSTRIDE;

    const int i = t & 127, hp = t >> 7;   // hp in {0,1}
    #pragma unroll
    for (int hh = 0; hh < 2; hh++) {
        int h = hp*2 + hh;
        const float* ph = part + h*PSTRIDE;
        float mm = -1e30f;
        #pragma unroll
        for (int c = 0; c < SPLIT; c++)
            mm = fmaxf(mm, ph[(size_t)c*H*PSTRIDE + F]);
        float vv = 0.f, ss = 0.f;
        #pragma unroll
        for (int c = 0; c < SPLIT; c++) {
            const float* pc = ph + (size_t)c*H*PSTRIDE;
            float e = __expf(pc[F] - mm);
            vv += pc[i] * e;
            ss += pc[F+1] * e;
        }
        pooled[h][i] = vv / ss;
    }
    __syncthreads();

    const float* Wsel[H] = {W1, W2, W3, W4};
    #pragma unroll
    for (int rep = 0; rep < 2; rep++) {
        int o = t + rep*256, h = o >> 7, j = o & 127;
        const float* Wh = Wsel[h];
        float acc = 0.f;
        #pragma unroll 8
        for (int iq = 0; iq < F; iq++) acc += pooled[h][iq] * Wh[iq*F + j];
        multi[o] = acc;
    }
    __syncthreads();

    const int oc = t & 63, seg = t >> 6;
    float acc = 0.f;
    #pragma unroll 8
    for (int kk = 0; kk < 128; kk++) {
        int k = seg*128 + kk;
        acc += multi[k] * Wo[k*64 + oc];
    }
    red[seg][oc] = acc;
    __syncthreads();
    if (t < 64) {
        float a = red[0][t] + red[1][t] + red[2][t] + red[3][t];
        out[grp*64 + t] = (a > 0.f) ? a : expm1f(a);
    }
}

// ---------------------------------------------------------------------------
extern "C" void kernel_launch(void* const* d_in, const int* in_sizes, int n_in,
                              void* d_out, int out_size) {
    const float* feat = (const float*)d_in[0];
    const float* W1   = (const float*)d_in[1];
    const float* a1   = (const float*)d_in[2];
    const float* W2   = (const float*)d_in[3];
    const float* a2   = (const float*)d_in[4];
    const float* W3   = (const float*)d_in[5];
    const float* a3   = (const float*)d_in[6];
    const float* W4   = (const float*)d_in[7];
    const float* a4   = (const float*)d_in[8];
    const float* Wo   = (const float*)d_in[9];
    float* out = (float*)d_out;

    k0_wa<<<4, 256>>>(W1, a1, W2, a2, W3, a3, W4, a4);
    kB_pool<<<dim3(NG, SPLIT), TB>>>(feat);
    k2_epi<<<NG, 256>>>(W1, W2, W3, W4, Wo, out);
}